// round 3
// baseline (speedup 1.0000x reference)
#include <cuda_runtime.h>
#include <math.h>

#define D    128
#define SEQ  200
#define BATCH 1024
#define NQV  50000
#define NCV  1000
#define NQD  101
#define NCD  101
#define RPC  8          // rows per CTA
#define NCTA (BATCH / RPC)

// ---------------- scratch (static device allocations only) ----------------
// 14 packed 128x128 weight blocks, layout pack[m][d4][j] = float4(W[j][off+4*d4 .. +3])
__device__ float4 g_pack[14 * 4096];            // 896 KB
__device__ float  g_EqP [NQV * D];              // Eq  @ WxA.T              (25.6 MB)
__device__ float  g_EcP [NCV * D];              // Ec  @ WxB.T
__device__ float  g_EqdP[NQD * D];              // Eqd @ WxC.T + bx
__device__ float  g_EcdP[NCD * D];              // Ecd @ WxD.T
__device__ float  g_CP1 [2 * D];                // Ecorr @ Wp1B.T + bp1
__device__ float  g_CP2 [2 * D];                // Ecorr @ Wp2B.T + bp2
__device__ float  g_Gc  [2 * D];                // Ecorr @ WkB.T  + bk
__device__ float  g_Gqd [NQD * D];              // Eqd   @ WkC.T
__device__ float  g_Gcd [NCD * D];              // Ecd   @ WkD.T

// ---------------- helpers ----------------
__device__ __forceinline__ float sigmoidf_(float x) {
    return __fdividef(1.0f, 1.0f + __expf(-x));
}
__device__ __forceinline__ float tanhf_(float x) {
    float t = __expf(-2.0f * fabsf(x));           // t in (0,1], overflow-safe
    float r = __fdividef(1.0f - t, 1.0f + t);
    return copysignf(r, x);
}

// ---------------- 1) weight packing ----------------
// grid (14, 32), block 128. pack[m][d4][j] = W[j][off + 4*d4 .. +3]
__global__ void pack_kernel(const float* __restrict__ Ws1, const float* __restrict__ Ws2,
                            const float* __restrict__ Wp1, const float* __restrict__ Wp2,
                            const float* __restrict__ Wk,  const float* __restrict__ Wx)
{
    const int m = blockIdx.x, d4 = blockIdx.y, j = threadIdx.x;
    const int srcsel[14] = {0,1,2,3,4, 5,5,5,5, 2,3, 4,4,4};
    const int strid [14] = {128,128,256,256,512, 512,512,512,512, 256,256, 512,512,512};
    const int offs  [14] = {0,0,0,0,0, 0,128,256,384, 128,128, 128,256,384};
    const float* srcs[6] = {Ws1, Ws2, Wp1, Wp2, Wk, Wx};
    const float* src = srcs[srcsel[m]];
    float4 v = *(const float4*)(src + (size_t)j * strid[m] + offs[m] + 4 * d4);
    g_pack[(m * 32 + d4) * 128 + j] = v;
}

// ---------------- 2) small table projections ----------------
__device__ __forceinline__ float* proj_out(int sel) {
    switch (sel) {
        case 0: return g_EqP;  case 1: return g_EcP;  case 2: return g_EqdP;
        case 3: return g_EcdP; case 4: return g_CP1;  case 5: return g_CP2;
        case 6: return g_Gc;   case 7: return g_Gqd;  default: return g_Gcd;
    }
}

// out[i][j] = (bias?bias[j]:0) + sum_d E[i][d] * packW[packIdx][d][j]
__global__ void proj_kernel(const float* __restrict__ E, int nrows, int packIdx,
                            const float* __restrict__ bias, int outSel)
{
    __shared__ __align__(16) float sE[16][D];
    const int j  = threadIdx.x;                 // 128 threads
    const int i0 = blockIdx.x * 16;
    int nr = nrows - i0; if (nr > 16) nr = 16;

    for (int k = threadIdx.x; k < 16 * (D / 4); k += 128) {
        int i = k >> 5, c4 = k & 31;
        float4 v = (i < nr) ? *(const float4*)(E + (size_t)(i0 + i) * D + 4 * c4)
                            : make_float4(0.f, 0.f, 0.f, 0.f);
        *(float4*)&sE[i][4 * c4] = v;
    }
    __syncthreads();

    float b = bias ? bias[j] : 0.0f;
    float acc[16];
    #pragma unroll
    for (int i = 0; i < 16; ++i) acc[i] = b;

    const float4* __restrict__ W = g_pack + (size_t)packIdx * 4096;
    #pragma unroll 4
    for (int d4 = 0; d4 < 32; ++d4) {
        const float4 w = W[d4 * 128 + j];
        #pragma unroll
        for (int i = 0; i < 16; ++i) {
            const float4 e = *(const float4*)&sE[i][4 * d4];
            acc[i] += w.x * e.x + w.y * e.y + w.z * e.z + w.w * e.w;
        }
    }
    float* out = proj_out(outSel);
    for (int i = 0; i < nr; ++i) out[(size_t)(i0 + i) * D + j] = acc[i];
}

// ---------------- 3) persistent scan ----------------
// grid 128, block 256. Threads split into 2 j-replicas (grp) x 4 rows each.
__global__ void __launch_bounds__(256, 1)
scan_kernel(const int* __restrict__ qseq,  const int* __restrict__ cseq,
            const int* __restrict__ qdseq, const int* __restrict__ cdseq,
            const int* __restrict__ corrseq,
            const float* __restrict__ bs1, const float* __restrict__ bs2,
            const float* __restrict__ h0,  float* __restrict__ y)
{
    __shared__ __align__(16) float s_sv [RPC][D];
    __shared__ __align__(16) float s_h  [RPC][D];
    __shared__ __align__(16) float s_sdf[RPC][D];
    __shared__ int   s_idx[RPC][7];   // [corr_t, qd_t, cd_t, q_{t+1}, c_{t+1}, qd_{t+1}, cd_{t+1}]
    __shared__ float s_red[8][4];     // per-warp partial dot sums

    const int tid  = threadIdx.x;
    const int j    = tid & (D - 1);
    const int grp  = tid >> 7;        // 0 or 1
    const int r0   = grp * 4;
    const int lane = tid & 31, warp = tid >> 5;
    const int rbase = blockIdx.x * RPC;

    const float4* __restrict__ W1  = g_pack + 0 * 4096;   // Ws1
    const float4* __restrict__ W2  = g_pack + 1 * 4096;   // Ws2
    const float4* __restrict__ WP1 = g_pack + 2 * 4096;   // Wp1A
    const float4* __restrict__ WP2 = g_pack + 3 * 4096;   // Wp2A
    const float4* __restrict__ WK  = g_pack + 4 * 4096;   // WkA

    float hreg[4], xreg[4];
    #pragma unroll
    for (int r = 0; r < 4; ++r) {
        hreg[r] = h0[(size_t)(rbase + r0 + r) * D + j];
        s_h[r0 + r][j] = hreg[r];
    }
    // x_0 (gather)
    #pragma unroll
    for (int r = 0; r < 4; ++r) {
        const int b  = rbase + r0 + r;
        const int q  = qseq [b * SEQ], c = cseq[b * SEQ];
        const int qd = qdseq[b * SEQ], cd = cdseq[b * SEQ];
        xreg[r] = g_EqP[q * D + j] + g_EcP[c * D + j] + g_EqdP[qd * D + j] + g_EcdP[cd * D + j];
    }
    if (tid < RPC) y[(size_t)(rbase + tid) * SEQ + (SEQ - 1)] = 0.0f;   // y[:, S-1] = 0
    const float bias1 = bs1[j], bias2 = bs2[j];

    for (int t = 0; t < SEQ - 1; ++t) {
        // indices for this step
        if (tid < RPC) {
            const int b = rbase + tid;
            const int base = b * SEQ + t;
            s_idx[tid][0] = corrseq[base];
            s_idx[tid][1] = qdseq [base];
            s_idx[tid][2] = cdseq [base];
            s_idx[tid][3] = qseq  [base + 1];
            s_idx[tid][4] = cseq  [base + 1];
            s_idx[tid][5] = qdseq [base + 1];
            s_idx[tid][6] = cdseq [base + 1];
        }
        // s_in = x_t - h_pre
        #pragma unroll
        for (int r = 0; r < 4; ++r) s_sv[r0 + r][j] = xreg[r] - hreg[r];
        __syncthreads();   // sv + idx + (h from prev step) visible

        // accumulator init (folded tables, biases inside)
        float a1[4], a2[4], c1[4];
        #pragma unroll
        for (int r = 0; r < 4; ++r) {
            const int ci = s_idx[r0 + r][0], qd = s_idx[r0 + r][1], cd = s_idx[r0 + r][2];
            a1[r] = bias1; a2[r] = bias2;
            c1[r] = g_Gc[ci * D + j] + g_Gqd[qd * D + j] + g_Gcd[cd * D + j];
        }
        // issue x_{t+1} gather loads early; consume after matvec (latency hidden under FMAs)
        float gx[4][4];
        #pragma unroll
        for (int r = 0; r < 4; ++r) {
            const int q  = s_idx[r0 + r][3], c  = s_idx[r0 + r][4];
            const int qd = s_idx[r0 + r][5], cd = s_idx[r0 + r][6];
            gx[r][0] = g_EqP [q  * D + j];
            gx[r][1] = g_EcP [c  * D + j];
            gx[r][2] = g_EqdP[qd * D + j];
            gx[r][3] = g_EcdP[cd * D + j];
        }

        // Phase A+C: a1 += Ws1*sv, a2 += Ws2*sv, c1 += WkA*h
        #pragma unroll 4
        for (int d4 = 0; d4 < 32; ++d4) {
            const float4 w1 = W1[d4 * 128 + j];
            const float4 w2 = W2[d4 * 128 + j];
            const float4 wk = WK[d4 * 128 + j];
            #pragma unroll
            for (int r = 0; r < 4; ++r) {
                const float4 sv = *(const float4*)&s_sv[r0 + r][4 * d4];
                const float4 hh = *(const float4*)&s_h [r0 + r][4 * d4];
                a1[r] += w1.x * sv.x + w1.y * sv.y + w1.z * sv.z + w1.w * sv.w;
                a2[r] += w2.x * sv.x + w2.y * sv.y + w2.z * sv.z + w2.w * sv.w;
                c1[r] += wk.x * hh.x + wk.y * hh.y + wk.z * hh.z + wk.w * hh.w;
            }
        }

        float g[4];
        #pragma unroll
        for (int r = 0; r < 4; ++r) {
            s_sdf[r0 + r][j] = sigmoidf_(a1[r]) * tanhf_(a2[r]);
            g[r] = sigmoidf_(c1[r]);
            xreg[r] = (gx[r][0] + gx[r][1]) + (gx[r][2] + gx[r][3]);  // x_{t+1}
        }
        __syncthreads();   // sdf visible

        // Phase B: b1/b2 = CPi[corr] + WpiA*sdf
        float b1[4], b2[4];
        #pragma unroll
        for (int r = 0; r < 4; ++r) {
            const int ci = s_idx[r0 + r][0];
            b1[r] = g_CP1[ci * D + j];
            b2[r] = g_CP2[ci * D + j];
        }
        #pragma unroll 4
        for (int d4 = 0; d4 < 32; ++d4) {
            const float4 p1 = WP1[d4 * 128 + j];
            const float4 p2 = WP2[d4 * 128 + j];
            #pragma unroll
            for (int r = 0; r < 4; ++r) {
                const float4 sd = *(const float4*)&s_sdf[r0 + r][4 * d4];
                b1[r] += p1.x * sd.x + p1.y * sd.y + p1.z * sd.z + p1.w * sd.w;
                b2[r] += p2.x * sd.x + p2.y * sd.y + p2.z * sd.z + p2.w * sd.w;
            }
        }

        // state update + prediction dot
        float prod[4];
        #pragma unroll
        for (int r = 0; r < 4; ++r) {
            const float pka = sigmoidf_(b1[r]) * tanhf_(b2[r]);
            const float hn  = g[r] * hreg[r] + (1.0f - g[r]) * pka;
            hreg[r] = hn;
            s_h[r0 + r][j] = hn;
            prod[r] = xreg[r] * hn;     // x_{t+1} . h_new
        }
        #pragma unroll
        for (int r = 0; r < 4; ++r) {
            float v = prod[r];
            v += __shfl_xor_sync(0xffffffffu, v, 16);
            v += __shfl_xor_sync(0xffffffffu, v, 8);
            v += __shfl_xor_sync(0xffffffffu, v, 4);
            v += __shfl_xor_sync(0xffffffffu, v, 2);
            v += __shfl_xor_sync(0xffffffffu, v, 1);
            if (lane == 0) s_red[warp][r] = v;
        }
        __syncthreads();   // s_red + new h visible

        if (tid < RPC) {
            const int gg = tid >> 2, rl = tid & 3;
            const float s = s_red[4 * gg + 0][rl] + s_red[4 * gg + 1][rl]
                          + s_red[4 * gg + 2][rl] + s_red[4 * gg + 3][rl];
            y[(size_t)(rbase + tid) * SEQ + t] = sigmoidf_(s);
        }
    }
}

// ---------------- launch ----------------
extern "C" void kernel_launch(void* const* d_in, const int* in_sizes, int n_in,
                              void* d_out, int out_size)
{
    const int*   qseq    = (const int*)  d_in[0];
    const int*   cseq    = (const int*)  d_in[1];
    const int*   qdseq   = (const int*)  d_in[2];
    const int*   cdseq   = (const int*)  d_in[3];
    const int*   corrseq = (const int*)  d_in[4];
    const float* Eq      = (const float*)d_in[5];
    const float* Ec      = (const float*)d_in[6];
    const float* Eqd     = (const float*)d_in[7];
    const float* Ecd     = (const float*)d_in[8];
    const float* Ecorr   = (const float*)d_in[9];
    const float* Wx      = (const float*)d_in[10];
    const float* bx      = (const float*)d_in[11];
    const float* Ws1     = (const float*)d_in[12];
    const float* bs1     = (const float*)d_in[13];
    const float* Ws2     = (const float*)d_in[14];
    const float* bs2     = (const float*)d_in[15];
    const float* Wp1     = (const float*)d_in[16];
    const float* bp1     = (const float*)d_in[17];
    const float* Wp2     = (const float*)d_in[18];
    const float* bp2     = (const float*)d_in[19];
    const float* Wk      = (const float*)d_in[20];
    const float* bk      = (const float*)d_in[21];
    const float* h0      = (const float*)d_in[22];
    float* y = (float*)d_out;

    // 1) pack all 128x128 weight blocks into [d4][j] float4 layout
    pack_kernel<<<dim3(14, 32), 128>>>(Ws1, Ws2, Wp1, Wp2, Wk, Wx);

    // 2) fold embedding tables through their weight blocks (biases folded in)
    proj_kernel<<<(NQV + 15) / 16, 128>>>(Eq,    NQV, 5,  nullptr, 0);  // EqP
    proj_kernel<<<(NCV + 15) / 16, 128>>>(Ec,    NCV, 6,  nullptr, 1);  // EcP
    proj_kernel<<<(NQD + 15) / 16, 128>>>(Eqd,   NQD, 7,  bx,      2);  // EqdP (+bx)
    proj_kernel<<<(NCD + 15) / 16, 128>>>(Ecd,   NCD, 8,  nullptr, 3);  // EcdP
    proj_kernel<<<1,               128>>>(Ecorr, 2,   9,  bp1,     4);  // CP1
    proj_kernel<<<1,               128>>>(Ecorr, 2,   10, bp2,     5);  // CP2
    proj_kernel<<<1,               128>>>(Ecorr, 2,   11, bk,      6);  // Gc
    proj_kernel<<<(NQD + 15) / 16, 128>>>(Eqd,   NQD, 12, nullptr, 7);  // Gqd
    proj_kernel<<<(NCD + 15) / 16, 128>>>(Ecd,   NCD, 13, nullptr, 8);  // Gcd

    // 3) persistent recurrent scan (rows independent -> no inter-CTA sync)
    scan_kernel<<<NCTA, 256>>>(qseq, cseq, qdseq, cdseq, corrseq, bs1, bs2, h0, y);
}

// round 8
// speedup vs baseline: 1.2341x; 1.2341x over previous
#include <cuda_runtime.h>
#include <math.h>

#define D     128
#define SEQ   200
#define BATCH 1024
#define NQV   50000
#define NCV   1000
#define NQD   101
#define NCD   101
#define RPC   8           // rows per CTA
#define NCTA  (BATCH / RPC)

typedef unsigned long long ull;

// ---------------- scratch (static device allocations only) ----------------
// 14 packed 128x128 weight blocks, layout pack[m][d4][j] = float4(W[j][4*d4 .. +3])
__device__ float4 g_pack[14 * 4096];            // 896 KB
__device__ float  g_EqP [NQV * D];              // Eq  @ WxA.T              (25.6 MB)
__device__ float  g_EcP [NCV * D];              // Ec  @ WxB.T
__device__ float  g_EqdP[NQD * D];              // Eqd @ WxC.T + bx
__device__ float  g_EcdP[NCD * D];              // Ecd @ WxD.T
__device__ float  g_CP1 [2 * D];                // Ecorr @ Wp1B.T + bp1
__device__ float  g_CP2 [2 * D];                // Ecorr @ Wp2B.T + bp2
__device__ float  g_Gc  [2 * D];                // Ecorr @ WkB.T  + bk
__device__ float  g_Gqd [NQD * D];              // Eqd   @ WkC.T
__device__ float  g_Gcd [NCD * D];              // Ecd   @ WkD.T

// ---------------- helpers ----------------
__device__ __forceinline__ float sigmoidf_(float x) {
    return __fdividef(1.0f, 1.0f + __expf(-x));
}
__device__ __forceinline__ float tanhf_(float x) {
    float t = __expf(-2.0f * fabsf(x));
    float r = __fdividef(1.0f - t, 1.0f + t);
    return copysignf(r, x);
}
// packed f32x2 primitives
__device__ __forceinline__ ull pack2f(float lo, float hi) {
    ull r;
    asm("mov.b64 %0, {%1, %2};" : "=l"(r)
        : "r"(__float_as_uint(lo)), "r"(__float_as_uint(hi)));
    return r;
}
__device__ __forceinline__ ull dup2f(float x) {
    ull r;
    asm("mov.b64 %0, {%1, %1};" : "=l"(r) : "r"(__float_as_uint(x)));
    return r;
}
__device__ __forceinline__ void fma2(ull &d, ull a, ull b) {
    asm("fma.rn.f32x2 %0, %1, %2, %0;" : "+l"(d) : "l"(a), "l"(b));
}
__device__ __forceinline__ float2 unpack2(ull v) {
    unsigned a, b;
    asm("mov.b64 {%0, %1}, %2;" : "=r"(a), "=r"(b) : "l"(v));
    return make_float2(__uint_as_float(a), __uint_as_float(b));
}

// ---------------- 1) weight packing ----------------
__global__ void pack_kernel(const float* __restrict__ Ws1, const float* __restrict__ Ws2,
                            const float* __restrict__ Wp1, const float* __restrict__ Wp2,
                            const float* __restrict__ Wk,  const float* __restrict__ Wx)
{
    const int m = blockIdx.x, d4 = blockIdx.y, j = threadIdx.x;
    const int srcsel[14] = {0,1,2,3,4, 5,5,5,5, 2,3, 4,4,4};
    const int strid [14] = {128,128,256,256,512, 512,512,512,512, 256,256, 512,512,512};
    const int offs  [14] = {0,0,0,0,0, 0,128,256,384, 128,128, 128,256,384};
    const float* srcs[6] = {Ws1, Ws2, Wp1, Wp2, Wk, Wx};
    const float* src = srcs[srcsel[m]];
    float4 v = *(const float4*)(src + (size_t)j * strid[m] + offs[m] + 4 * d4);
    g_pack[(m * 32 + d4) * 128 + j] = v;
}

// ---------------- 2) small table projections ----------------
__device__ __forceinline__ float* proj_out(int sel) {
    switch (sel) {
        case 0: return g_EqP;  case 1: return g_EcP;  case 2: return g_EqdP;
        case 3: return g_EcdP; case 4: return g_CP1;  case 5: return g_CP2;
        case 6: return g_Gc;   case 7: return g_Gqd;  default: return g_Gcd;
    }
}

__global__ void proj_kernel(const float* __restrict__ E, int nrows, int packIdx,
                            const float* __restrict__ bias, int outSel)
{
    __shared__ __align__(16) float sE[16][D];
    const int j  = threadIdx.x;
    const int i0 = blockIdx.x * 16;
    int nr = nrows - i0; if (nr > 16) nr = 16;

    for (int k = threadIdx.x; k < 16 * (D / 4); k += 128) {
        int i = k >> 5, c4 = k & 31;
        float4 v = (i < nr) ? *(const float4*)(E + (size_t)(i0 + i) * D + 4 * c4)
                            : make_float4(0.f, 0.f, 0.f, 0.f);
        *(float4*)&sE[i][4 * c4] = v;
    }
    __syncthreads();

    float b = bias ? bias[j] : 0.0f;
    float acc[16];
    #pragma unroll
    for (int i = 0; i < 16; ++i) acc[i] = b;

    const float4* __restrict__ W = g_pack + (size_t)packIdx * 4096;
    #pragma unroll 4
    for (int d4 = 0; d4 < 32; ++d4) {
        const float4 w = W[d4 * 128 + j];
        #pragma unroll
        for (int i = 0; i < 16; ++i) {
            const float4 e = *(const float4*)&sE[i][4 * d4];
            acc[i] += w.x * e.x + w.y * e.y + w.z * e.z + w.w * e.w;
        }
    }
    float* out = proj_out(outSel);
    for (int i = 0; i < nr; ++i) out[(size_t)(i0 + i) * D + j] = acc[i];
}

// ---------------- 3) persistent scan (d-split + f32x2) ----------------
// 256 threads = 2 d-halves x 128 output dims j.
// Thread (half, j): owns state h/x for rows 4*half..4*half+3 at dim j, and
// computes partial dots over d in [64*half, 64*half+64) for ALL 8 rows.
// Row pairs packed in f32x2: pair p holds rows {2p, 2p+1} in {lo, hi}.
#define SW_F4     12288                      // 3 mats * 4096 float4 (Ws1,Ws2,Wk)
#define SMEM_BYTES (196608 + 3*4096 + 12288 + 256 + 128)

__global__ void __launch_bounds__(256, 1)
scan_kernel(const int* __restrict__ qseq,  const int* __restrict__ cseq,
            const int* __restrict__ qdseq, const int* __restrict__ cdseq,
            const int* __restrict__ corrseq,
            const float* __restrict__ bs1, const float* __restrict__ bs2,
            const float* __restrict__ h0,  float* __restrict__ y)
{
    extern __shared__ __align__(16) unsigned char smem_raw[];
    float4* sW     = (float4*)smem_raw;                       // [0..12288) float4
    ull*    s_sv2  = (ull*)(smem_raw + 196608);               // [4][128] row-pair f32x2
    ull*    s_h2   = s_sv2 + 512;
    ull*    s_sdf2 = s_h2  + 512;
    ull*    s_red  = s_sdf2 + 512;                            // [3][4][128]
    int*    s_idx  = (int*)(s_red + 1536);                    // [8][7]
    float*  s_yred = (float*)(s_idx + 64);                    // [8 warps][4]

    const int tid  = threadIdx.x;
    const int j    = tid & (D - 1);
    const int half = tid >> 7;                 // 0 or 1
    const int lane = tid & 31, warp = tid >> 5;
    const int rbase = blockIdx.x * RPC;
    const int h16  = half * 16;                // d4 range [h16, h16+16)
    const int po   = 2 * half;                 // own pairs po, po+1
    const int qo   = 2 - 2 * half;             // other half's pairs

    const float4* __restrict__ sW1 = sW;            // Ws1
    const float4* __restrict__ sW2 = sW + 4096;     // Ws2
    const float4* __restrict__ sWk = sW + 8192;     // WkA
    const float4* __restrict__ WP1 = g_pack + 2 * 4096;   // Wp1A (streamed)
    const float4* __restrict__ WP2 = g_pack + 3 * 4096;   // Wp2A (streamed)

    // stage Ws1, Ws2, Wk into shared (once)
    for (int i = tid; i < SW_F4; i += 256)
        ((float4*)sW)[i] = (i < 8192) ? g_pack[i] : g_pack[4 * 4096 + (i - 8192)];

    const float bias1 = bs1[j], bias2 = bs2[j];

    // init own-row state (rows 4*half + 0..3)
    float h[4], x[4];
    #pragma unroll
    for (int rl = 0; rl < 4; ++rl) {
        const int b = rbase + 4 * half + rl;
        h[rl] = h0[(size_t)b * D + j];
        const int q  = qseq [b * SEQ], c  = cseq [b * SEQ];
        const int qd = qdseq[b * SEQ], cd = cdseq[b * SEQ];
        x[rl] = g_EqP[q * D + j] + g_EcP[c * D + j] + g_EqdP[qd * D + j] + g_EcdP[cd * D + j];
    }
    if (tid < RPC) y[(size_t)(rbase + tid) * SEQ + (SEQ - 1)] = 0.0f;

    for (int t = 0; t < SEQ - 1; ++t) {
        // ---- (a) publish sv, h and this step's indices ----
        if (tid < RPC) {
            const int base = (rbase + tid) * SEQ + t;
            s_idx[tid * 7 + 0] = corrseq[base];
            s_idx[tid * 7 + 1] = qdseq [base];
            s_idx[tid * 7 + 2] = cdseq [base];
            s_idx[tid * 7 + 3] = qseq  [base + 1];
            s_idx[tid * 7 + 4] = cseq  [base + 1];
            s_idx[tid * 7 + 5] = qdseq [base + 1];
            s_idx[tid * 7 + 6] = cdseq [base + 1];
        }
        s_sv2[(po + 0) * 128 + j] = pack2f(x[0] - h[0], x[1] - h[1]);
        s_sv2[(po + 1) * 128 + j] = pack2f(x[2] - h[2], x[3] - h[3]);
        s_h2 [(po + 0) * 128 + j] = pack2f(h[0], h[1]);
        s_h2 [(po + 1) * 128 + j] = pack2f(h[2], h[3]);
        __syncthreads();                                         // #1

        // ---- early gathers for own rows (latency hidden under the matvecs) ----
        float gx[4][4], gG[4], cp1[4], cp2[4];
        #pragma unroll
        for (int rl = 0; rl < 4; ++rl) {
            const int r = 4 * half + rl;
            const int ci = s_idx[r * 7 + 0], qd = s_idx[r * 7 + 1], cd = s_idx[r * 7 + 2];
            gG [rl] = g_Gc[ci * D + j] + g_Gqd[qd * D + j] + g_Gcd[cd * D + j];
            cp1[rl] = g_CP1[ci * D + j];
            cp2[rl] = g_CP2[ci * D + j];
            const int q2  = s_idx[r * 7 + 3], c2  = s_idx[r * 7 + 4];
            const int qd2 = s_idx[r * 7 + 5], cd2 = s_idx[r * 7 + 6];
            gx[rl][0] = g_EqP [q2  * D + j];
            gx[rl][1] = g_EcP [c2  * D + j];
            gx[rl][2] = g_EqdP[qd2 * D + j];
            gx[rl][3] = g_EcdP[cd2 * D + j];
        }

        // ---- (b) Phase A+C: a1=Ws1*sv, a2=Ws2*sv, c1=Wk*h  (partial over my d-half)
        ull a1[4] = {0,0,0,0}, a2[4] = {0,0,0,0}, c1[4] = {0,0,0,0};
        #pragma unroll 4
        for (int dd = 0; dd < 16; ++dd) {
            const int d4 = h16 + dd;
            const float4 w1 = sW1[d4 * 128 + j];
            const float4 w2 = sW2[d4 * 128 + j];
            const float4 wk = sWk[d4 * 128 + j];
            const ull w1x = dup2f(w1.x), w1y = dup2f(w1.y), w1z = dup2f(w1.z), w1w = dup2f(w1.w);
            const ull w2x = dup2f(w2.x), w2y = dup2f(w2.y), w2z = dup2f(w2.z), w2w = dup2f(w2.w);
            const ull wkx = dup2f(wk.x), wky = dup2f(wk.y), wkz = dup2f(wk.z), wkw = dup2f(wk.w);
            #pragma unroll
            for (int p = 0; p < 4; ++p) {
                const ulonglong2 sA = *(const ulonglong2*)(s_sv2 + p * 128 + 4 * d4);
                const ulonglong2 sB = *(const ulonglong2*)(s_sv2 + p * 128 + 4 * d4 + 2);
                const ulonglong2 hA = *(const ulonglong2*)(s_h2  + p * 128 + 4 * d4);
                const ulonglong2 hB = *(const ulonglong2*)(s_h2  + p * 128 + 4 * d4 + 2);
                fma2(a1[p], w1x, sA.x); fma2(a1[p], w1y, sA.y);
                fma2(a1[p], w1z, sB.x); fma2(a1[p], w1w, sB.y);
                fma2(a2[p], w2x, sA.x); fma2(a2[p], w2y, sA.y);
                fma2(a2[p], w2z, sB.x); fma2(a2[p], w2w, sB.y);
                fma2(c1[p], wkx, hA.x); fma2(c1[p], wky, hA.y);
                fma2(c1[p], wkz, hB.x); fma2(c1[p], wkw, hB.y);
            }
        }
        // hand the other half's pairs to it
        s_red[(0 * 4 + qo + 0) * 128 + j] = a1[qo + 0];
        s_red[(0 * 4 + qo + 1) * 128 + j] = a1[qo + 1];
        s_red[(1 * 4 + qo + 0) * 128 + j] = a2[qo + 0];
        s_red[(1 * 4 + qo + 1) * 128 + j] = a2[qo + 1];
        s_red[(2 * 4 + qo + 0) * 128 + j] = c1[qo + 0];
        s_red[(2 * 4 + qo + 1) * 128 + j] = c1[qo + 1];
        __syncthreads();                                         // #2

        // ---- (c) combine own pairs -> sdf (to smem), g (regs) ----
        float g[4];
        #pragma unroll
        for (int pl = 0; pl < 2; ++pl) {
            const int p = po + pl;
            const float2 m1 = unpack2(a1[p]), r1 = unpack2(s_red[(0 * 4 + p) * 128 + j]);
            const float2 m2 = unpack2(a2[p]), r2 = unpack2(s_red[(1 * 4 + p) * 128 + j]);
            const float2 mc = unpack2(c1[p]), rc = unpack2(s_red[(2 * 4 + p) * 128 + j]);
            const float a1L = m1.x + r1.x + bias1, a1H = m1.y + r1.y + bias1;
            const float a2L = m2.x + r2.x + bias2, a2H = m2.y + r2.y + bias2;
            const float sdfL = sigmoidf_(a1L) * tanhf_(a2L);
            const float sdfH = sigmoidf_(a1H) * tanhf_(a2H);
            s_sdf2[p * 128 + j] = pack2f(sdfL, sdfH);
            g[2 * pl + 0] = sigmoidf_(mc.x + rc.x + gG[2 * pl + 0]);
            g[2 * pl + 1] = sigmoidf_(mc.y + rc.y + gG[2 * pl + 1]);
        }
        __syncthreads();                                         // #3

        // ---- (d) Phase B: b1=Wp1*sdf, b2=Wp2*sdf (Wp streamed, 2-deep prefetch)
        ull b1[4] = {0,0,0,0}, b2[4] = {0,0,0,0};
        float4 f1[2], f2[2];
        f1[0] = WP1[(h16 + 0) * 128 + j];  f2[0] = WP2[(h16 + 0) * 128 + j];
        f1[1] = WP1[(h16 + 1) * 128 + j];  f2[1] = WP2[(h16 + 1) * 128 + j];
        #pragma unroll 2
        for (int dd = 0; dd < 16; ++dd) {
            const int d4 = h16 + dd;
            const float4 w1 = f1[dd & 1], w2 = f2[dd & 1];
            if (dd + 2 < 16) {
                f1[dd & 1] = WP1[(d4 + 2) * 128 + j];
                f2[dd & 1] = WP2[(d4 + 2) * 128 + j];
            }
            const ull p1x = dup2f(w1.x), p1y = dup2f(w1.y), p1z = dup2f(w1.z), p1w = dup2f(w1.w);
            const ull p2x = dup2f(w2.x), p2y = dup2f(w2.y), p2z = dup2f(w2.z), p2w = dup2f(w2.w);
            #pragma unroll
            for (int p = 0; p < 4; ++p) {
                const ulonglong2 dA = *(const ulonglong2*)(s_sdf2 + p * 128 + 4 * d4);
                const ulonglong2 dB = *(const ulonglong2*)(s_sdf2 + p * 128 + 4 * d4 + 2);
                fma2(b1[p], p1x, dA.x); fma2(b1[p], p1y, dA.y);
                fma2(b1[p], p1z, dB.x); fma2(b1[p], p1w, dB.y);
                fma2(b2[p], p2x, dA.x); fma2(b2[p], p2y, dA.y);
                fma2(b2[p], p2z, dB.x); fma2(b2[p], p2w, dB.y);
            }
        }
        s_red[(0 * 4 + qo + 0) * 128 + j] = b1[qo + 0];
        s_red[(0 * 4 + qo + 1) * 128 + j] = b1[qo + 1];
        s_red[(1 * 4 + qo + 0) * 128 + j] = b2[qo + 0];
        s_red[(1 * 4 + qo + 1) * 128 + j] = b2[qo + 1];
        __syncthreads();                                         // #4

        // ---- (e) combine -> pka -> h update; x_{t+1}; y dot ----
        float prod[4];
        #pragma unroll
        for (int pl = 0; pl < 2; ++pl) {
            const int p = po + pl;
            const float2 mb1 = unpack2(b1[p]), rb1 = unpack2(s_red[(0 * 4 + p) * 128 + j]);
            const float2 mb2 = unpack2(b2[p]), rb2 = unpack2(s_red[(1 * 4 + p) * 128 + j]);
            const float b1L = mb1.x + rb1.x + cp1[2 * pl + 0];
            const float b1H = mb1.y + rb1.y + cp1[2 * pl + 1];
            const float b2L = mb2.x + rb2.x + cp2[2 * pl + 0];
            const float b2H = mb2.y + rb2.y + cp2[2 * pl + 1];
            const float pkaL = sigmoidf_(b1L) * tanhf_(b2L);
            const float pkaH = sigmoidf_(b1H) * tanhf_(b2H);
            const int rl = 2 * pl;
            h[rl + 0] = g[rl + 0] * h[rl + 0] + (1.0f - g[rl + 0]) * pkaL;
            h[rl + 1] = g[rl + 1] * h[rl + 1] + (1.0f - g[rl + 1]) * pkaH;
        }
        #pragma unroll
        for (int rl = 0; rl < 4; ++rl) {
            x[rl] = (gx[rl][0] + gx[rl][1]) + (gx[rl][2] + gx[rl][3]);   // x_{t+1}
            prod[rl] = x[rl] * h[rl];
        }
        #pragma unroll
        for (int rl = 0; rl < 4; ++rl) {
            float v = prod[rl];
            v += __shfl_xor_sync(0xffffffffu, v, 16);
            v += __shfl_xor_sync(0xffffffffu, v, 8);
            v += __shfl_xor_sync(0xffffffffu, v, 4);
            v += __shfl_xor_sync(0xffffffffu, v, 2);
            v += __shfl_xor_sync(0xffffffffu, v, 1);
            if (lane == 0) s_yred[warp * 4 + rl] = v;
        }
        __syncthreads();                                         // #5

        if (tid < RPC) {
            const int r = tid, hh = r >> 2, rl = r & 3;
            const float s = s_yred[(4 * hh + 0) * 4 + rl] + s_yred[(4 * hh + 1) * 4 + rl]
                          + s_yred[(4 * hh + 2) * 4 + rl] + s_yred[(4 * hh + 3) * 4 + rl];
            y[(size_t)(rbase + r) * SEQ + t] = sigmoidf_(s);
        }
    }
}

// ---------------- launch ----------------
extern "C" void kernel_launch(void* const* d_in, const int* in_sizes, int n_in,
                              void* d_out, int out_size)
{
    const int*   qseq    = (const int*)  d_in[0];
    const int*   cseq    = (const int*)  d_in[1];
    const int*   qdseq   = (const int*)  d_in[2];
    const int*   cdseq   = (const int*)  d_in[3];
    const int*   corrseq = (const int*)  d_in[4];
    const float* Eq      = (const float*)d_in[5];
    const float* Ec      = (const float*)d_in[6];
    const float* Eqd     = (const float*)d_in[7];
    const float* Ecd     = (const float*)d_in[8];
    const float* Ecorr   = (const float*)d_in[9];
    const float* Wx      = (const float*)d_in[10];
    const float* bx      = (const float*)d_in[11];
    const float* Ws1     = (const float*)d_in[12];
    const float* bs1     = (const float*)d_in[13];
    const float* Ws2     = (const float*)d_in[14];
    const float* bs2     = (const float*)d_in[15];
    const float* Wp1     = (const float*)d_in[16];
    const float* bp1     = (const float*)d_in[17];
    const float* Wp2     = (const float*)d_in[18];
    const float* bp2     = (const float*)d_in[19];
    const float* Wk      = (const float*)d_in[20];
    const float* bk      = (const float*)d_in[21];
    const float* h0      = (const float*)d_in[22];
    float* y = (float*)d_out;

    static int smem_set = 0;
    if (!smem_set) {
        cudaFuncSetAttribute(scan_kernel, cudaFuncAttributeMaxDynamicSharedMemorySize,
                             SMEM_BYTES);
        smem_set = 1;
    }

    // 1) pack all 128x128 weight blocks into [d4][j] float4 layout
    pack_kernel<<<dim3(14, 32), 128>>>(Ws1, Ws2, Wp1, Wp2, Wk, Wx);

    // 2) fold embedding tables through their weight blocks (biases folded in)
    proj_kernel<<<(NQV + 15) / 16, 128>>>(Eq,    NQV, 5,  nullptr, 0);  // EqP
    proj_kernel<<<(NCV + 15) / 16, 128>>>(Ec,    NCV, 6,  nullptr, 1);  // EcP
    proj_kernel<<<(NQD + 15) / 16, 128>>>(Eqd,   NQD, 7,  bx,      2);  // EqdP (+bx)
    proj_kernel<<<(NCD + 15) / 16, 128>>>(Ecd,   NCD, 8,  nullptr, 3);  // EcdP
    proj_kernel<<<1,               128>>>(Ecorr, 2,   9,  bp1,     4);  // CP1
    proj_kernel<<<1,               128>>>(Ecorr, 2,   10, bp2,     5);  // CP2
    proj_kernel<<<1,               128>>>(Ecorr, 2,   11, bk,      6);  // Gc
    proj_kernel<<<(NQD + 15) / 16, 128>>>(Eqd,   NQD, 12, nullptr, 7);  // Gqd
    proj_kernel<<<(NCD + 15) / 16, 128>>>(Ecd,   NCD, 13, nullptr, 8);  // Gcd

    // 3) persistent recurrent scan (rows independent -> no inter-CTA sync)
    scan_kernel<<<NCTA, 256, SMEM_BYTES>>>(qseq, cseq, qdseq, cdseq, corrseq,
                                           bs1, bs2, h0, y);
}

// round 12
// speedup vs baseline: 1.4562x; 1.1800x over previous
#include <cuda_runtime.h>
#include <math.h>

#define D     128
#define SEQ   200
#define BATCH 1024
#define NQV   50000
#define NCV   1000
#define NQD   101
#define NCD   101
#define RPC   8           // rows per CTA
#define NCTA  (BATCH / RPC)
#define NTHR  512         // 4 d-quarters x 128 output dims

typedef unsigned long long ull;

// ---------------- scratch (static device allocations only) ----------------
// 14 packed 128x128 weight blocks, layout pack[m][d4][j] = float4(W[j][4*d4 .. +3])
__device__ float4 g_pack[14 * 4096];            // 896 KB
__device__ float  g_EqP [NQV * D];              // Eq  @ WxA.T              (25.6 MB)
__device__ float  g_EcP [NCV * D];              // Ec  @ WxB.T
__device__ float  g_EqdP[NQD * D];              // Eqd @ WxC.T + bx
__device__ float  g_EcdP[NCD * D];              // Ecd @ WxD.T
__device__ float  g_CP1 [2 * D];                // Ecorr @ Wp1B.T + bp1
__device__ float  g_CP2 [2 * D];                // Ecorr @ Wp2B.T + bp2
__device__ float  g_Gc  [2 * D];                // Ecorr @ WkB.T  + bk
__device__ float  g_Gqd [NQD * D];              // Eqd   @ WkC.T
__device__ float  g_Gcd [NCD * D];              // Ecd   @ WkD.T

// ---------------- helpers ----------------
__device__ __forceinline__ float sigmoidf_(float x) {
    return __fdividef(1.0f, 1.0f + __expf(-x));
}
__device__ __forceinline__ float tanhf_(float x) {
    float t = __expf(-2.0f * fabsf(x));
    float r = __fdividef(1.0f - t, 1.0f + t);
    return copysignf(r, x);
}
// packed f32x2 primitives
__device__ __forceinline__ ull pack2f(float lo, float hi) {
    ull r;
    asm("mov.b64 %0, {%1, %2};" : "=l"(r)
        : "r"(__float_as_uint(lo)), "r"(__float_as_uint(hi)));
    return r;
}
__device__ __forceinline__ ull dup2f(float x) {
    ull r;
    asm("mov.b64 %0, {%1, %1};" : "=l"(r) : "r"(__float_as_uint(x)));
    return r;
}
__device__ __forceinline__ void fma2(ull &d, ull a, ull b) {
    asm("fma.rn.f32x2 %0, %1, %2, %0;" : "+l"(d) : "l"(a), "l"(b));
}
__device__ __forceinline__ float2 unpack2(ull v) {
    unsigned a, b;
    asm("mov.b64 {%0, %1}, %2;" : "=r"(a), "=r"(b) : "l"(v));
    return make_float2(__uint_as_float(a), __uint_as_float(b));
}

// ---------------- 1) weight packing ----------------
__global__ void pack_kernel(const float* __restrict__ Ws1, const float* __restrict__ Ws2,
                            const float* __restrict__ Wp1, const float* __restrict__ Wp2,
                            const float* __restrict__ Wk,  const float* __restrict__ Wx)
{
    const int m = blockIdx.x, d4 = blockIdx.y, j = threadIdx.x;
    const int srcsel[14] = {0,1,2,3,4, 5,5,5,5, 2,3, 4,4,4};
    const int strid [14] = {128,128,256,256,512, 512,512,512,512, 256,256, 512,512,512};
    const int offs  [14] = {0,0,0,0,0, 0,128,256,384, 128,128, 128,256,384};
    const float* srcs[6] = {Ws1, Ws2, Wp1, Wp2, Wk, Wx};
    const float* src = srcs[srcsel[m]];
    float4 v = *(const float4*)(src + (size_t)j * strid[m] + offs[m] + 4 * d4);
    g_pack[(m * 32 + d4) * 128 + j] = v;
}

// ---------------- 2) small table projections ----------------
__device__ __forceinline__ float* proj_out(int sel) {
    switch (sel) {
        case 0: return g_EqP;  case 1: return g_EcP;  case 2: return g_EqdP;
        case 3: return g_EcdP; case 4: return g_CP1;  case 5: return g_CP2;
        case 6: return g_Gc;   case 7: return g_Gqd;  default: return g_Gcd;
    }
}

__global__ void proj_kernel(const float* __restrict__ E, int nrows, int packIdx,
                            const float* __restrict__ bias, int outSel)
{
    __shared__ __align__(16) float sE[16][D];
    const int j  = threadIdx.x;
    const int i0 = blockIdx.x * 16;
    int nr = nrows - i0; if (nr > 16) nr = 16;

    for (int k = threadIdx.x; k < 16 * (D / 4); k += 128) {
        int i = k >> 5, c4 = k & 31;
        float4 v = (i < nr) ? *(const float4*)(E + (size_t)(i0 + i) * D + 4 * c4)
                            : make_float4(0.f, 0.f, 0.f, 0.f);
        *(float4*)&sE[i][4 * c4] = v;
    }
    __syncthreads();

    float b = bias ? bias[j] : 0.0f;
    float acc[16];
    #pragma unroll
    for (int i = 0; i < 16; ++i) acc[i] = b;

    const float4* __restrict__ W = g_pack + (size_t)packIdx * 4096;
    #pragma unroll 4
    for (int d4 = 0; d4 < 32; ++d4) {
        const float4 w = W[d4 * 128 + j];
        #pragma unroll
        for (int i = 0; i < 16; ++i) {
            const float4 e = *(const float4*)&sE[i][4 * d4];
            acc[i] += w.x * e.x + w.y * e.y + w.z * e.z + w.w * e.w;
        }
    }
    float* out = proj_out(outSel);
    for (int i = 0; i < nr; ++i) out[(size_t)(i0 + i) * D + j] = acc[i];
}

// ---------------- 3) persistent scan (d-quarters + f32x2) ----------------
// 512 threads = 4 d-quarters (q) x 128 output dims (j).
// Thread (q, j): owns state h/x for rows {2q, 2q+1} at dim j (pair q), and
// computes partial dots over d in [32q, 32q+32) for ALL 4 row pairs.
// Row pairs in f32x2: pair p holds rows {2p, 2p+1} in {lo, hi}.
// Ws1, Ws2 live in smem; Wk, Wp1, Wp2 stream from L2 with prefetch.
#define SMEM_SW_B   131072                   // Ws1+Ws2: 8192 float4
#define SMEM_BYTES  (SMEM_SW_B + 3*4096 + 49152 + 256 + 128)

__global__ void __launch_bounds__(NTHR, 1)
scan_kernel(const int* __restrict__ qseq,  const int* __restrict__ cseq,
            const int* __restrict__ qdseq, const int* __restrict__ cdseq,
            const int* __restrict__ corrseq,
            const float* __restrict__ bs1, const float* __restrict__ bs2,
            const float* __restrict__ h0,  float* __restrict__ y)
{
    extern __shared__ __align__(16) unsigned char smem_raw[];
    float4* sW     = (float4*)smem_raw;                       // [0..8192) float4
    ull*    s_sv2  = (ull*)(smem_raw + SMEM_SW_B);            // [4 pairs][128]
    ull*    s_h2   = s_sv2 + 512;
    ull*    s_sdf2 = s_h2  + 512;
    ull*    s_red  = s_sdf2 + 512;                            // [3][4 pairs][4 q][128]
    int*    s_idx  = (int*)(s_red + 6144);                    // [8][7]
    float*  s_yred = (float*)(s_idx + 64);                    // [16 warps][2]

    const int tid  = threadIdx.x;
    const int j    = tid & (D - 1);
    const int q    = tid >> 7;                 // d-quarter 0..3, own pair q
    const int lane = tid & 31, warp = tid >> 5;
    const int rbase = blockIdx.x * RPC;
    const int r0   = 2 * q;                    // own rows r0, r0+1
    const int dd0  = q * 8;                    // d4 range [dd0, dd0+8)

    const float4* __restrict__ sW1 = sW;             // Ws1 (smem)
    const float4* __restrict__ sW2 = sW + 4096;      // Ws2 (smem)
    const float4* __restrict__ gWk = g_pack + 4 * 4096;   // WkA  (streamed)
    const float4* __restrict__ WP1 = g_pack + 2 * 4096;   // Wp1A (streamed)
    const float4* __restrict__ WP2 = g_pack + 3 * 4096;   // Wp2A (streamed)

    // stage Ws1, Ws2 into shared (once)
    for (int i = tid; i < 8192; i += NTHR) sW[i] = g_pack[i];

    const float bias1 = bs1[j], bias2 = bs2[j];

    // init own-row state (rows 2q, 2q+1)
    float h[2], x[2];
    #pragma unroll
    for (int rl = 0; rl < 2; ++rl) {
        const int b = rbase + r0 + rl;
        h[rl] = h0[(size_t)b * D + j];
        const int qi = qseq [b * SEQ], c  = cseq [b * SEQ];
        const int qd = qdseq[b * SEQ], cd = cdseq[b * SEQ];
        x[rl] = g_EqP[qi * D + j] + g_EcP[c * D + j] + g_EqdP[qd * D + j] + g_EcdP[cd * D + j];
    }
    if (tid < RPC) y[(size_t)(rbase + tid) * SEQ + (SEQ - 1)] = 0.0f;   // y[:, S-1]=0

    for (int t = 0; t < SEQ - 1; ++t) {
        // ---- (a) publish sv, h and this step's indices ----
        if (tid < RPC) {
            const int base = (rbase + tid) * SEQ + t;
            s_idx[tid * 7 + 0] = corrseq[base];
            s_idx[tid * 7 + 1] = qdseq [base];
            s_idx[tid * 7 + 2] = cdseq [base];
            s_idx[tid * 7 + 3] = qseq  [base + 1];
            s_idx[tid * 7 + 4] = cseq  [base + 1];
            s_idx[tid * 7 + 5] = qdseq [base + 1];
            s_idx[tid * 7 + 6] = cdseq [base + 1];
        }
        s_sv2[q * 128 + j] = pack2f(x[0] - h[0], x[1] - h[1]);
        s_h2 [q * 128 + j] = pack2f(h[0], h[1]);
        __syncthreads();                                         // #1

        // ---- early gathers for own rows (consumed in (c)/(e), hidden under matvecs)
        float gx[2][4], gG[2], cp1v[2], cp2v[2];
        #pragma unroll
        for (int rl = 0; rl < 2; ++rl) {
            const int r = r0 + rl;
            const int ci = s_idx[r * 7 + 0], qd = s_idx[r * 7 + 1], cd = s_idx[r * 7 + 2];
            gG  [rl] = g_Gc[ci * D + j] + g_Gqd[qd * D + j] + g_Gcd[cd * D + j];
            cp1v[rl] = g_CP1[ci * D + j];
            cp2v[rl] = g_CP2[ci * D + j];
            const int q2  = s_idx[r * 7 + 3], c2  = s_idx[r * 7 + 4];
            const int qd2 = s_idx[r * 7 + 5], cd2 = s_idx[r * 7 + 6];
            gx[rl][0] = g_EqP [q2  * D + j];
            gx[rl][1] = g_EcP [c2  * D + j];
            gx[rl][2] = g_EqdP[qd2 * D + j];
            gx[rl][3] = g_EcdP[cd2 * D + j];
        }

        // ---- (b) Phase A+C: a1=Ws1*sv, a2=Ws2*sv, c1=Wk*h over my d-quarter
        ull a1[4] = {0,0,0,0}, a2[4] = {0,0,0,0}, c1[4] = {0,0,0,0};
        float4 wkpf[2];
        wkpf[0] = gWk[(dd0 + 0) * 128 + j];
        wkpf[1] = gWk[(dd0 + 1) * 128 + j];
        #pragma unroll 4
        for (int dd = 0; dd < 8; ++dd) {
            const int d4 = dd0 + dd;
            const float4 w1 = sW1[d4 * 128 + j];
            const float4 w2 = sW2[d4 * 128 + j];
            const float4 wk = wkpf[dd & 1];
            if (dd + 2 < 8) wkpf[dd & 1] = gWk[(d4 + 2) * 128 + j];
            const ull w1x = dup2f(w1.x), w1y = dup2f(w1.y), w1z = dup2f(w1.z), w1w = dup2f(w1.w);
            const ull w2x = dup2f(w2.x), w2y = dup2f(w2.y), w2z = dup2f(w2.z), w2w = dup2f(w2.w);
            const ull wkx = dup2f(wk.x), wky = dup2f(wk.y), wkz = dup2f(wk.z), wkw = dup2f(wk.w);
            #pragma unroll
            for (int p = 0; p < 4; ++p) {
                const ulonglong2 sA = *(const ulonglong2*)(s_sv2 + p * 128 + 4 * d4);
                const ulonglong2 sB = *(const ulonglong2*)(s_sv2 + p * 128 + 4 * d4 + 2);
                const ulonglong2 hA = *(const ulonglong2*)(s_h2  + p * 128 + 4 * d4);
                const ulonglong2 hB = *(const ulonglong2*)(s_h2  + p * 128 + 4 * d4 + 2);
                fma2(a1[p], w1x, sA.x); fma2(a1[p], w1y, sA.y);
                fma2(a1[p], w1z, sB.x); fma2(a1[p], w1w, sB.y);
                fma2(a2[p], w2x, sA.x); fma2(a2[p], w2y, sA.y);
                fma2(a2[p], w2z, sB.x); fma2(a2[p], w2w, sB.y);
                fma2(c1[p], wkx, hA.x); fma2(c1[p], wky, hA.y);
                fma2(c1[p], wkz, hB.x); fma2(c1[p], wkw, hB.y);
            }
        }
        // publish all partials: s_red[((m*4 + p)*4 + q)*128 + j]
        #pragma unroll
        for (int p = 0; p < 4; ++p) {
            s_red[((0 * 4 + p) * 4 + q) * 128 + j] = a1[p];
            s_red[((1 * 4 + p) * 4 + q) * 128 + j] = a2[p];
            s_red[((2 * 4 + p) * 4 + q) * 128 + j] = c1[p];
        }
        __syncthreads();                                         // #2

        // ---- (c) combine own pair q -> sdf (smem), g (regs) ----
        float g[2];
        {
            float a1L = bias1, a1H = bias1, a2L = bias2, a2H = bias2;
            float c1L = gG[0], c1H = gG[1];
            #pragma unroll
            for (int qq = 0; qq < 4; ++qq) {
                const float2 v1 = unpack2(s_red[((0 * 4 + q) * 4 + qq) * 128 + j]);
                const float2 v2 = unpack2(s_red[((1 * 4 + q) * 4 + qq) * 128 + j]);
                const float2 vc = unpack2(s_red[((2 * 4 + q) * 4 + qq) * 128 + j]);
                a1L += v1.x; a1H += v1.y;
                a2L += v2.x; a2H += v2.y;
                c1L += vc.x; c1H += vc.y;
            }
            const float sdfL = sigmoidf_(a1L) * tanhf_(a2L);
            const float sdfH = sigmoidf_(a1H) * tanhf_(a2H);
            s_sdf2[q * 128 + j] = pack2f(sdfL, sdfH);
            g[0] = sigmoidf_(c1L);
            g[1] = sigmoidf_(c1H);
        }
        __syncthreads();                                         // #3

        // ---- (d) Phase B: b1=Wp1*sdf, b2=Wp2*sdf (streamed, 2-deep prefetch)
        ull b1[4] = {0,0,0,0}, b2[4] = {0,0,0,0};
        float4 f1[2], f2[2];
        f1[0] = WP1[(dd0 + 0) * 128 + j];  f2[0] = WP2[(dd0 + 0) * 128 + j];
        f1[1] = WP1[(dd0 + 1) * 128 + j];  f2[1] = WP2[(dd0 + 1) * 128 + j];
        #pragma unroll 4
        for (int dd = 0; dd < 8; ++dd) {
            const int d4 = dd0 + dd;
            const float4 w1 = f1[dd & 1], w2 = f2[dd & 1];
            if (dd + 2 < 8) {
                f1[dd & 1] = WP1[(d4 + 2) * 128 + j];
                f2[dd & 1] = WP2[(d4 + 2) * 128 + j];
            }
            const ull p1x = dup2f(w1.x), p1y = dup2f(w1.y), p1z = dup2f(w1.z), p1w = dup2f(w1.w);
            const ull p2x = dup2f(w2.x), p2y = dup2f(w2.y), p2z = dup2f(w2.z), p2w = dup2f(w2.w);
            #pragma unroll
            for (int p = 0; p < 4; ++p) {
                const ulonglong2 dA = *(const ulonglong2*)(s_sdf2 + p * 128 + 4 * d4);
                const ulonglong2 dB = *(const ulonglong2*)(s_sdf2 + p * 128 + 4 * d4 + 2);
                fma2(b1[p], p1x, dA.x); fma2(b1[p], p1y, dA.y);
                fma2(b1[p], p1z, dB.x); fma2(b1[p], p1w, dB.y);
                fma2(b2[p], p2x, dA.x); fma2(b2[p], p2y, dA.y);
                fma2(b2[p], p2z, dB.x); fma2(b2[p], p2w, dB.y);
            }
        }
        #pragma unroll
        for (int p = 0; p < 4; ++p) {
            s_red[((0 * 4 + p) * 4 + q) * 128 + j] = b1[p];
            s_red[((1 * 4 + p) * 4 + q) * 128 + j] = b2[p];
        }
        __syncthreads();                                         // #4

        // ---- (e) combine -> pka -> h update; x_{t+1}; y dot ----
        {
            float b1L = cp1v[0], b1H = cp1v[1];
            float b2L = cp2v[0], b2H = cp2v[1];
            #pragma unroll
            for (int qq = 0; qq < 4; ++qq) {
                const float2 v1 = unpack2(s_red[((0 * 4 + q) * 4 + qq) * 128 + j]);
                const float2 v2 = unpack2(s_red[((1 * 4 + q) * 4 + qq) * 128 + j]);
                b1L += v1.x; b1H += v1.y;
                b2L += v2.x; b2H += v2.y;
            }
            const float pkaL = sigmoidf_(b1L) * tanhf_(b2L);
            const float pkaH = sigmoidf_(b1H) * tanhf_(b2H);
            h[0] = g[0] * h[0] + (1.0f - g[0]) * pkaL;
            h[1] = g[1] * h[1] + (1.0f - g[1]) * pkaH;
        }
        float prod[2];
        #pragma unroll
        for (int rl = 0; rl < 2; ++rl) {
            x[rl] = (gx[rl][0] + gx[rl][1]) + (gx[rl][2] + gx[rl][3]);   // x_{t+1}
            prod[rl] = x[rl] * h[rl];
        }
        #pragma unroll
        for (int rl = 0; rl < 2; ++rl) {
            float v = prod[rl];
            v += __shfl_xor_sync(0xffffffffu, v, 16);
            v += __shfl_xor_sync(0xffffffffu, v, 8);
            v += __shfl_xor_sync(0xffffffffu, v, 4);
            v += __shfl_xor_sync(0xffffffffu, v, 2);
            v += __shfl_xor_sync(0xffffffffu, v, 1);
            if (lane == 0) s_yred[warp * 2 + rl] = v;
        }
        __syncthreads();                                         // #5

        if (tid < RPC) {
            const int r = tid, qr = r >> 1, rl = r & 1;
            const float s = s_yred[(4 * qr + 0) * 2 + rl] + s_yred[(4 * qr + 1) * 2 + rl]
                          + s_yred[(4 * qr + 2) * 2 + rl] + s_yred[(4 * qr + 3) * 2 + rl];
            y[(size_t)(rbase + r) * SEQ + t] = sigmoidf_(s);
        }
    }
}

// ---------------- launch ----------------
extern "C" void kernel_launch(void* const* d_in, const int* in_sizes, int n_in,
                              void* d_out, int out_size)
{
    const int*   qseq    = (const int*)  d_in[0];
    const int*   cseq    = (const int*)  d_in[1];
    const int*   qdseq   = (const int*)  d_in[2];
    const int*   cdseq   = (const int*)  d_in[3];
    const int*   corrseq = (const int*)  d_in[4];
    const float* Eq      = (const float*)d_in[5];
    const float* Ec      = (const float*)d_in[6];
    const float* Eqd     = (const float*)d_in[7];
    const float* Ecd     = (const float*)d_in[8];
    const float* Ecorr   = (const float*)d_in[9];
    const float* Wx      = (const float*)d_in[10];
    const float* bx      = (const float*)d_in[11];
    const float* Ws1     = (const float*)d_in[12];
    const float* bs1     = (const float*)d_in[13];
    const float* Ws2     = (const float*)d_in[14];
    const float* bs2     = (const float*)d_in[15];
    const float* Wp1     = (const float*)d_in[16];
    const float* bp1     = (const float*)d_in[17];
    const float* Wp2     = (const float*)d_in[18];
    const float* bp2     = (const float*)d_in[19];
    const float* Wk      = (const float*)d_in[20];
    const float* bk      = (const float*)d_in[21];
    const float* h0      = (const float*)d_in[22];
    float* y = (float*)d_out;

    static int smem_set = 0;
    if (!smem_set) {
        cudaFuncSetAttribute(scan_kernel, cudaFuncAttributeMaxDynamicSharedMemorySize,
                             SMEM_BYTES);
        smem_set = 1;
    }

    // 1) pack all 128x128 weight blocks into [d4][j] float4 layout
    pack_kernel<<<dim3(14, 32), 128>>>(Ws1, Ws2, Wp1, Wp2, Wk, Wx);

    // 2) fold embedding tables through their weight blocks (biases folded in)
    proj_kernel<<<(NQV + 15) / 16, 128>>>(Eq,    NQV, 5,  nullptr, 0);  // EqP
    proj_kernel<<<(NCV + 15) / 16, 128>>>(Ec,    NCV, 6,  nullptr, 1);  // EcP
    proj_kernel<<<(NQD + 15) / 16, 128>>>(Eqd,   NQD, 7,  bx,      2);  // EqdP (+bx)
    proj_kernel<<<(NCD + 15) / 16, 128>>>(Ecd,   NCD, 8,  nullptr, 3);  // EcdP
    proj_kernel<<<1,               128>>>(Ecorr, 2,   9,  bp1,     4);  // CP1
    proj_kernel<<<1,               128>>>(Ecorr, 2,   10, bp2,     5);  // CP2
    proj_kernel<<<1,               128>>>(Ecorr, 2,   11, bk,      6);  // Gc
    proj_kernel<<<(NQD + 15) / 16, 128>>>(Eqd,   NQD, 12, nullptr, 7);  // Gqd
    proj_kernel<<<(NCD + 15) / 16, 128>>>(Ecd,   NCD, 13, nullptr, 8);  // Gcd

    // 3) persistent recurrent scan (rows independent -> no inter-CTA sync)
    scan_kernel<<<NCTA, NTHR, SMEM_BYTES>>>(qseq, cseq, qdseq, cdseq, corrseq,
                                            bs1, bs2, h0, y);
}